// round 6
// baseline (speedup 1.0000x reference)
#include <cuda_runtime.h>
#include <cstdint>

// Ragged segment mean — fire-and-forget TMA bulk streaming.
//   seq: [B=2048, L=512, D=512] f32; out[b] = mean(seq[b, begin[b]:end[b]])
//
// Grid = (B, L/32). CTA (b,c) covers chunk c (32 rows, contiguous 64KB max)
// ∩ [begin,end). ALL bulk copies (2 stages x <=16 rows) are issued by
// thread 0 immediately at CTA start; the consumer just waits+reduces.
// No syncthreads / re-issue in the hot path. Pre-scale by 1/n, RED.v4 out.

static constexpr int L = 512;
static constexpr int D = 512;
static constexpr int D4 = D / 4;            // 128 float4 per row
static constexpr int THREADS = 128;
static constexpr int CHUNK = 32;
static constexpr int NCHUNK = L / CHUNK;    // 16
static constexpr int SROWS = 16;            // rows per stage (32KB)
static constexpr int ROW_BYTES = D * 4;     // 2048

__device__ __forceinline__ uint32_t smem_u32(const void* p) {
    return (uint32_t)__cvta_generic_to_shared(p);
}
__device__ __forceinline__ void mbar_init(uint32_t a, uint32_t cnt) {
    asm volatile("mbarrier.init.shared.b64 [%0], %1;" :: "r"(a), "r"(cnt) : "memory");
}
__device__ __forceinline__ void mbar_expect_tx(uint32_t a, uint32_t bytes) {
    asm volatile("mbarrier.arrive.expect_tx.shared.b64 _, [%0], %1;"
                 :: "r"(a), "r"(bytes) : "memory");
}
__device__ __forceinline__ void mbar_wait0(uint32_t a) {
    uint32_t done;
    asm volatile("{\n\t.reg .pred p;\n\t"
                 "mbarrier.try_wait.parity.acquire.cta.shared::cta.b64 p, [%1], 0;\n\t"
                 "selp.b32 %0, 1, 0, p;\n\t}"
                 : "=r"(done) : "r"(a) : "memory");
    while (!done) {
        asm volatile("{\n\t.reg .pred p;\n\t"
                     "mbarrier.try_wait.parity.acquire.cta.shared::cta.b64 p, [%1], 0, 10000000;\n\t"
                     "selp.b32 %0, 1, 0, p;\n\t}"
                     : "=r"(done) : "r"(a) : "memory");
    }
}
__device__ __forceinline__ void bulk_g2s(uint32_t dst, const void* src,
                                         uint32_t bytes, uint32_t mbar) {
    asm volatile("cp.async.bulk.shared::cluster.global.mbarrier::complete_tx::bytes "
                 "[%0], [%1], %2, [%3];"
                 :: "r"(dst), "l"(src), "r"(bytes), "r"(mbar) : "memory");
}
__device__ __forceinline__ void red_add_v4(float* addr, float4 v) {
    asm volatile("red.global.add.v4.f32 [%0], {%1, %2, %3, %4};"
                 :: "l"(addr), "f"(v.x), "f"(v.y), "f"(v.z), "f"(v.w)
                 : "memory");
}
__device__ __forceinline__ void acc4(float4& a, const float4& v) {
    a.x += v.x; a.y += v.y; a.z += v.z; a.w += v.w;
}

__global__ __launch_bounds__(THREADS)
void ragged_mean_ff_kernel(const float* __restrict__ seq,
                           const int* __restrict__ begin,
                           const int* __restrict__ end,
                           float* __restrict__ out) {
    __shared__ alignas(1024) float4 buf[2][SROWS * D4];  // 2 x 32KB
    __shared__ alignas(8) uint64_t mbar_s[2];

    const int b = blockIdx.x;
    const int c = blockIdx.y;
    const int s = __ldg(begin + b);
    const int e = __ldg(end + b);

    const int lo = max(s, c * CHUNK);
    const int hi = min(e, (c + 1) * CHUNK);
    if (lo >= hi) return;

    const int nrows = hi - lo;
    const int n0 = min(SROWS, nrows);
    const int n1 = nrows - n0;             // 0..16
    const int t = threadIdx.x;

    const uint32_t mb0 = smem_u32(&mbar_s[0]);
    const uint32_t mb1 = smem_u32(&mbar_s[1]);

    if (t == 0) { mbar_init(mb0, 1); mbar_init(mb1, 1); }
    __syncthreads();

    const char* src =
        (const char*)seq + ((size_t)b * L + (size_t)lo) * ROW_BYTES;

    // Fire ALL copy work immediately; nothing else to issue afterwards.
    if (t == 0) {
        mbar_expect_tx(mb0, (uint32_t)n0 * ROW_BYTES);
        bulk_g2s(smem_u32(&buf[0][0]), src, (uint32_t)n0 * ROW_BYTES, mb0);
        if (n1 > 0) {
            mbar_expect_tx(mb1, (uint32_t)n1 * ROW_BYTES);
            bulk_g2s(smem_u32(&buf[1][0]), src + (size_t)n0 * ROW_BYTES,
                     (uint32_t)n1 * ROW_BYTES, mb1);
        }
    }

    float4 a0 = make_float4(0.f, 0.f, 0.f, 0.f);
    float4 a1 = make_float4(0.f, 0.f, 0.f, 0.f);
    float4 a2 = make_float4(0.f, 0.f, 0.f, 0.f);
    float4 a3 = make_float4(0.f, 0.f, 0.f, 0.f);

    // Stage 0
    mbar_wait0(mb0);
    {
        const float4* bp = &buf[0][t];
        if (n0 == SROWS) {
            #pragma unroll
            for (int r = 0; r < SROWS; r += 4) {
                float4 v0 = bp[(r + 0) * D4];
                float4 v1 = bp[(r + 1) * D4];
                float4 v2 = bp[(r + 2) * D4];
                float4 v3 = bp[(r + 3) * D4];
                acc4(a0, v0); acc4(a1, v1); acc4(a2, v2); acc4(a3, v3);
            }
        } else {
            for (int r = 0; r < n0; ++r) acc4(a0, bp[r * D4]);
        }
    }

    // Stage 1
    if (n1 > 0) {
        mbar_wait0(mb1);
        const float4* bp = &buf[1][t];
        if (n1 == SROWS) {
            #pragma unroll
            for (int r = 0; r < SROWS; r += 4) {
                float4 v0 = bp[(r + 0) * D4];
                float4 v1 = bp[(r + 1) * D4];
                float4 v2 = bp[(r + 2) * D4];
                float4 v3 = bp[(r + 3) * D4];
                acc4(a0, v0); acc4(a1, v1); acc4(a2, v2); acc4(a3, v3);
            }
        } else {
            for (int r = 0; r < n1; ++r) acc4(a1, bp[r * D4]);
        }
    }

    const float inv = 1.0f / (float)(e - s);
    float4 p;
    p.x = (a0.x + a1.x + a2.x + a3.x) * inv;
    p.y = (a0.y + a1.y + a2.y + a3.y) * inv;
    p.z = (a0.z + a1.z + a2.z + a3.z) * inv;
    p.w = (a0.w + a1.w + a2.w + a3.w) * inv;

    red_add_v4(out + ((size_t)b * D4 + t) * 4, p);
}

extern "C" void kernel_launch(void* const* d_in, const int* in_sizes, int n_in,
                              void* d_out, int out_size) {
    const float* seq  = (const float*)d_in[0];
    const int* begin  = (const int*)d_in[1];
    const int* end    = (const int*)d_in[2];
    float* out        = (float*)d_out;

    const int B = in_sizes[1];  // 2048

    cudaMemsetAsync(d_out, 0, (size_t)out_size * sizeof(float));

    dim3 grid(B, NCHUNK);
    ragged_mean_ff_kernel<<<grid, THREADS>>>(seq, begin, end, out);
}